// round 16
// baseline (speedup 1.0000x reference)
#include <cuda_runtime.h>
#include <cuda_bf16.h>
#include <cstdint>

typedef unsigned long long ULL;

// ---------------- helpers ----------------
__device__ __forceinline__ uint32_t smem_u32(const void* p) {
    uint32_t a;
    asm("{ .reg .u64 t; cvta.to.shared.u64 t, %1; cvt.u32.u64 %0, t; }" : "=r"(a) : "l"(p));
    return a;
}
__device__ __forceinline__ void fma2(ULL &d, ULL a, ULL b) {
    asm("fma.rn.f32x2 %0, %1, %2, %0;" : "+l"(d) : "l"(a), "l"(b));
}
__device__ __forceinline__ ULL dup2(float f) {
    ULL r; asm("mov.b64 %0, {%1, %1};" : "=l"(r) : "f"(f)); return r;
}
__device__ __forceinline__ float2 unpk(ULL v) {
    float2 r; asm("mov.b64 {%0, %1}, %2;" : "=f"(r.x), "=f"(r.y) : "l"(v)); return r;
}
__device__ __forceinline__ uint32_t bf2pack(float a, float b) {
    __nv_bfloat162 t = __floats2bfloat162_rn(a, b);
    return *reinterpret_cast<uint32_t*>(&t);
}
__device__ __forceinline__ float ex2f(float x) {
    float r; asm("ex2.approx.ftz.f32 %0, %1;" : "=f"(r) : "f"(x)); return r;
}

#define LDSM4(r, addr) \
    asm volatile("ldmatrix.sync.aligned.m8n8.x4.shared.b16 {%0,%1,%2,%3}, [%4];" \
        : "=r"((r)[0]), "=r"((r)[1]), "=r"((r)[2]), "=r"((r)[3]) : "r"(addr))
#define LDSM4T(r, addr) \
    asm volatile("ldmatrix.sync.aligned.m8n8.x4.trans.shared.b16 {%0,%1,%2,%3}, [%4];" \
        : "=r"((r)[0]), "=r"((r)[1]), "=r"((r)[2]), "=r"((r)[3]) : "r"(addr))
#define MMA16816(c, a, b0, b1) \
    asm volatile("mma.sync.aligned.m16n8k16.row.col.f32.bf16.bf16.f32 " \
        "{%0,%1,%2,%3}, {%4,%5,%6,%7}, {%8,%9}, {%0,%1,%2,%3};" \
        : "+f"((c)[0]), "+f"((c)[1]), "+f"((c)[2]), "+f"((c)[3]) \
        : "r"((a)[0]), "r"((a)[1]), "r"((a)[2]), "r"((a)[3]), "r"(b0), "r"(b1))

#define CP_ASYNC16(dst, src) \
    asm volatile("cp.async.cg.shared.global [%0], [%1], 16;" :: "r"(dst), "l"(src) : "memory")
#define CP_COMMIT() asm volatile("cp.async.commit_group;" ::: "memory")
#define CP_WAIT1()  asm volatile("cp.async.wait_group 1;" ::: "memory")
#define CP_WAIT0()  asm volatile("cp.async.wait_group 0;" ::: "memory")

// ---------------- problem constants ----------------
#define BB 4
#define SS 1024
#define HH 4
#define HD 128
#define PIT 132

// ---------------- device scratch ----------------
__device__ float g_svec[64];
__device__ __nv_bfloat16 g_qb[BB*HH*SS*HD];   // y_q only, scaled by log2e/sqrt(hd)
__device__ __nv_bfloat16 g_kb[BB*HH*SS*HD];   // y_k only
__device__ __nv_bfloat16 g_vb[BB*HH*SS*HD];   // y_v only (s re-added via sum(w)=1)
__device__ float g_pw[BB*HH*SS];              // normalized pos softmax weights

// ---------------- K1: projections (by 0..3) + posb (by==4) + svec (by==5) ----------------
__global__ __launch_bounds__(256) void k_projposb(
    const float* __restrict__ x,
    const float* __restrict__ qw, const float* __restrict__ kw,
    const float* __restrict__ vw, const int* __restrict__ embid,
    const float* __restrict__ pos,
    const float* __restrict__ w1, const float* __restrict__ b1,
    const float* __restrict__ w2, const float* __restrict__ b2,
    const float* __restrict__ hw,
    const float* __restrict__ strength,
    const float* __restrict__ str_w, const float* __restrict__ str_b)
{
    __shared__ __align__(16) char psm[16384 + 3*8192 + 256];
    const int tid = threadIdx.x;

    if (blockIdx.y == 5) {        // ---- strength projection: one channel per block ----
        float* red8 = (float*)psm;
        const int d = blockIdx.x;
        const int l = tid & 31, w = tid >> 5;
        float2 a  = *(const float2*)(str_w + d*512 + tid*2);
        float2 s2 = *(const float2*)(strength + tid*2);
        float s = a.x*s2.x + a.y*s2.y;
        #pragma unroll
        for (int ofs = 1; ofs < 32; ofs <<= 1)
            s += __shfl_xor_sync(0xffffffffu, s, ofs);
        if (l == 0) red8[w] = s;
        __syncthreads();
        if (tid == 0) {
            float t = 0.f;
            #pragma unroll
            for (int j = 0; j < 8; j++) t += red8[j];
            g_svec[d] = t + str_b[d];
        }
        return;
    }

    if (blockIdx.y == 4) {        // ---- positional softmax weights ----
        if (blockIdx.x >= 16) return;
        float* sn  = (float*)psm;        // 1024
        float* red = sn + 1024;          // 256
        const int bh = blockIdx.x, bp = bh >> 2, hp = bh & 3;

        float hwv[8];
        #pragma unroll
        for (int d = 0; d < 8; d++) hwv[d] = hw[hp*8 + d];

        for (int s = tid; s < 1024; s += 256) {
            int idx = bp*1024 + s;
            float p0 = pos[idx*3+0], p1 = pos[idx*3+1], p2 = pos[idx*3+2];
            float h1[3];
            #pragma unroll
            for (int j = 0; j < 3; j++)
                h1[j] = fmaxf(0.f, w1[j*3+0]*p0 + w1[j*3+1]*p1 + w1[j*3+2]*p2 + b1[j]);
            float a = 0.f;
            #pragma unroll
            for (int d = 0; d < 8; d++) {
                float ph = w2[d*3+0]*h1[0] + w2[d*3+1]*h1[1] + w2[d*3+2]*h1[2] + b2[d];
                a += ph * hwv[d];
            }
            sn[s] = -a;     // head_b cancels in softmax
        }
        __syncthreads();

        float mx = fmaxf(fmaxf(sn[tid], sn[tid+256]), fmaxf(sn[tid+512], sn[tid+768]));
        red[tid] = mx; __syncthreads();
        for (int st = 128; st > 0; st >>= 1) { if (tid < st) red[tid] = fmaxf(red[tid], red[tid+st]); __syncthreads(); }
        mx = red[0]; __syncthreads();

        float e0 = __expf(sn[tid      ] - mx), e1 = __expf(sn[tid + 256] - mx);
        float e2 = __expf(sn[tid + 512] - mx), e3 = __expf(sn[tid + 768] - mx);
        red[tid] = e0 + e1 + e2 + e3; __syncthreads();
        for (int st = 128; st > 0; st >>= 1) { if (tid < st) red[tid] += red[tid+st]; __syncthreads(); }
        float inv = 1.f / red[0];

        size_t base = (size_t)bh*1024;
        g_pw[base + tid      ] = e0 * inv;
        g_pw[base + tid + 256] = e1 * inv;
        g_pw[base + tid + 512] = e2 * inv;
        g_pw[base + tid + 768] = e3 * inv;
        return;
    }

    // ---- projections: 128 m-rows (16 s x 8 w) at s0 = bx*16 ----
    const uint32_t sbp = smem_u32(psm);
    const int bx = blockIdx.x, b = blockIdx.y;
    const int s0 = bx * 16;
    const int wid = tid >> 5, l = tid & 31;
    const int id = embid[0];

    {
        const float* xb = x + (size_t)(b*64)*8192 + (size_t)s0*8;
        for (int i = tid; i < 2048; i += 256) {
            int c = i >> 5, mf = (i & 31) << 2;
            float4 v = *(const float4*)(xb + (size_t)c*8192 + mf);
            uint2 u = { bf2pack(v.x, v.y), bf2pack(v.z, v.w) };
            *(uint2*)(psm + c*256 + ((((mf>>3)) ^ (c & 7)) << 4) + (mf & 7)*2) = u;
        }
    }
    {
        const float* es[3] = { qw + (size_t)id*4096, kw + (size_t)id*4096, vw + (size_t)id*4096 };
        #pragma unroll
        for (int e = 0; e < 3; e++) {
            char* eb = psm + 16384 + e*8192;
            for (int i = tid; i < 1024; i += 256) {
                int d = i >> 4, cf = (i & 15) << 2;
                float4 v = *(const float4*)(es[e] + d*64 + cf);
                uint2 u = { bf2pack(v.x, v.y), bf2pack(v.z, v.w) };
                *(uint2*)(eb + d*128 + (((cf>>3) ^ (d & 7)) << 4) + (cf & 7)*2) = u;
            }
        }
    }
    __syncthreads();

    const int lr = l & 7, lb8 = (l >> 3) & 1, lb16 = l >> 4;
    const int mb = wid * 16;

    uint32_t af[4][4];
    #pragma unroll
    for (int ks = 0; ks < 4; ks++) {
        uint32_t ad = sbp + (uint32_t)(ks*16 + lr + (lb16 << 3))*256
                    + ((((uint32_t)(mb >> 3) + (uint32_t)lb8) ^ (uint32_t)lr) << 4);
        LDSM4T(af[ks], ad);
    }

    float cc[3][8][4];
    #pragma unroll
    for (int e = 0; e < 3; e++)
        #pragma unroll
        for (int nt = 0; nt < 8; nt++)
            #pragma unroll
            for (int j = 0; j < 4; j++) cc[e][nt][j] = 0.f;

    #pragma unroll
    for (int ks = 0; ks < 4; ks++) {
        #pragma unroll
        for (int e = 0; e < 3; e++) {
            const uint32_t ebB = sbp + 16384 + (uint32_t)e*8192
                               + (uint32_t)(lr + (lb16 << 3))*128;
            #pragma unroll
            for (int n4 = 0; n4 < 4; n4++) {
                uint32_t bfr[4];
                uint32_t ad = ebB + (uint32_t)n4*2048
                            + ((((uint32_t)(ks << 1) | (uint32_t)lb8) ^ (uint32_t)lr) << 4);
                LDSM4(bfr, ad);
                MMA16816(cc[e][n4*2],     af[ks], bfr[0], bfr[1]);
                MMA16816(cc[e][n4*2 + 1], af[ks], bfr[2], bfr[3]);
            }
        }
    }

    const float SC = 0.12751744817759326f;   // log2(e)/sqrt(128)
    const int q0 = l & 3, lr2 = l >> 2;
    #pragma unroll
    for (int rr = 0; rr < 2; rr++) {
        int m = mb + lr2 + rr*8;
        int sl = m >> 3, w = m & 7;
        int h = w >> 1;
        int bh = b*4 + h;
        int jb = (w & 1) << 6;
        size_t base = ((size_t)bh*1024 + (s0 + sl))*128 + jb;
        #pragma unroll
        for (int nt = 0; nt < 8; nt++) {
            int d = nt*8 + q0*2;
            *(uint32_t*)&g_qb[base + d] = bf2pack(cc[0][nt][rr*2]*SC, cc[0][nt][rr*2 + 1]*SC);
            *(uint32_t*)&g_kb[base + d] = bf2pack(cc[1][nt][rr*2], cc[1][nt][rr*2 + 1]);
            *(uint32_t*)&g_vb[base + d] = bf2pack(cc[2][nt][rr*2], cc[2][nt][rr*2 + 1]);
        }
    }
}

// ---------------- K2: bf16 mma.sync flash attention + fused pv + rank-1 s·K correction ----------------
#define SQO 0
#define SK0 32768
#define SK1 65536
#define SV0 98304
#define SV1 131072
#define SADD 165888
#define LPART 166400
#define OWT 166912
#define PVACC 184832
#define PWALL 193024
#define SKVS 197120
#define SSCL 197632
#define OT_F 24576          // float index of byte 98304
#define ATTN_SMEM 198144

__global__ __launch_bounds__(512) void k_attn(
    const float* __restrict__ gate, const float* __restrict__ out_w,
    const float* __restrict__ out_b, float* __restrict__ out)
{
    extern __shared__ char smc[];
    float* smf = (float*)smc;
    const uint32_t sb = smem_u32(smc);
    const int stile = blockIdx.x, bh = blockIdx.y;
    const int b = bh >> 2, h = bh & 3;
    const int s0 = stile * 128;
    const int tid = threadIdx.x, wid = tid >> 5, l = tid & 31;
    const int lr = l & 7, lb8 = (l >> 3) & 1, lb16 = l >> 4;
    const int wm = wid & 7, whalf = wid >> 3;   // key-half split

    const float SC = 0.12751744817759326f;     // log2(e)/sqrt(128)
    const float gv  = 1.f / (1.f + __expf(-gate[h]));
    const float omg = 1.f - gv;
    float* sAdd  = (float*)(smc + SADD);
    float* lpart = (float*)(smc + LPART);
    float* pvacc = (float*)(smc + PVACC);
    float* pwAll = (float*)(smc + PWALL);   // 1024 pos weights for this bh
    float* skvs  = (float*)(smc + SKVS);    // per-key s·K·SC correction
    float* sScl  = (float*)(smc + SSCL);    // svec[d&63]*SC

    const int tg = tid >> 5;
    const int d4 = l << 2;
    float4 pva = {0.f, 0.f, 0.f, 0.f};

    // ---- preload pos weights + scaled svec (once) ----
    for (int i = tid; i < 1024; i += 512) pwAll[i] = g_pw[(size_t)bh*1024 + i];
    if (tid < 128) sScl[tid] = g_svec[tid & 63] * SC;

    // ---- stage Q (once) ----
    const __nv_bfloat16* Qb = g_qb + (size_t)bh*131072 + (size_t)s0*128;
    for (int i = tid; i < 2048; i += 512) {
        int r = i >> 4, cc = i & 15;
        *(uint4*)(smc + SQO + r*256 + ((cc ^ (r & 7)) << 4)) =
            *(const uint4*)(Qb + (size_t)r*128 + cc*8);
    }

    const __nv_bfloat16* Kb = g_kb + (size_t)bh*131072;
    const __nv_bfloat16* Vb = g_vb + (size_t)bh*131072;

    // prefetch chunk 0
    {
        const uint32_t kB = sb + SK0, vB = sb + SV0;
        for (int i = tid; i < 2048; i += 512) {
            int r = i >> 4, cc = i & 15;
            uint32_t sw = (uint32_t)(r*256 + ((cc ^ (r & 7)) << 4));
            CP_ASYNC16(kB + sw, Kb + (size_t)r*128 + cc*8);
            CP_ASYNC16(vB + sw, Vb + (size_t)r*128 + cc*8);
        }
        CP_COMMIT();
    }
    __syncthreads();   // Q + pwAll + sScl visible

    const int mb = wm * 16;
    const int arow = mb + lr + (lb8 << 3);
    const uint32_t aBase = sb + SQO + arow*256;

    float oacc[16][4];
    #pragma unroll
    for (int i = 0; i < 16; i++)
        #pragma unroll
        for (int j = 0; j < 4; j++) oacc[i][j] = 0.f;
    float lsum0 = 0.f, lsum1 = 0.f;

    for (int c = 0; c < 8; c++) {
        if (c < 7) {
            const int t0n = (c + 1) * 128;
            const uint32_t kB = sb + (((c + 1) & 1) ? SK1 : SK0);
            const uint32_t vB = sb + (((c + 1) & 1) ? SV1 : SV0);
            for (int i = tid; i < 2048; i += 512) {
                int r = i >> 4, cc = i & 15;
                uint32_t sw = (uint32_t)(r*256 + ((cc ^ (r & 7)) << 4));
                CP_ASYNC16(kB + sw, Kb + (size_t)(t0n + r)*128 + cc*8);
                CP_ASYNC16(vB + sw, Vb + (size_t)(t0n + r)*128 + cc*8);
            }
            CP_COMMIT();
            CP_WAIT1();
        } else {
            CP_WAIT0();
        }
        __syncthreads();

        const char* kbufc = smc + ((c & 1) ? SK1 : SK0);
        const uint32_t kRowB = sb + ((c & 1) ? SK1 : SK0) + (uint32_t)(lr + (lb16 << 3))*256;
        const uint32_t vRowB = sb + ((c & 1) ? SV1 : SV0) + (uint32_t)(lr + (lb8  << 3))*256;

        // ---- skv[t] = sum_d sScl[d] * K[t][d]  (4 threads per key) ----
        {
            const int t = tid >> 2, p = tid & 3;
            float acc = 0.f;
            #pragma unroll
            for (int q8 = 0; q8 < 4; q8++) {
                int cc2 = p*4 + q8;
                uint4 raw = *(const uint4*)(kbufc + t*256 + (((uint32_t)cc2 ^ (uint32_t)(t & 7)) << 4));
                const __nv_bfloat162* kb2 = (const __nv_bfloat162*)&raw;
                const float* sc = sScl + cc2*8;
                #pragma unroll
                for (int u = 0; u < 4; u++) {
                    float2 f = __bfloat1622float2(kb2[u]);
                    acc += f.x*sc[u*2] + f.y*sc[u*2 + 1];
                }
            }
            acc += __shfl_xor_sync(0xffffffffu, acc, 1);
            acc += __shfl_xor_sync(0xffffffffu, acc, 2);
            if (p == 0) skvs[t] = acc;
        }

        // ---- S = Q @ K^T (m16 x my 64-key half) ----
        float sacc[8][4];
        #pragma unroll
        for (int i = 0; i < 8; i++)
            #pragma unroll
            for (int j = 0; j < 4; j++) sacc[i][j] = 0.f;

        #pragma unroll
        for (int ks = 0; ks < 8; ks++) {
            uint32_t aq[4];
            LDSM4(aq, aBase + (((uint32_t)((ks << 1) | lb16) ^ (uint32_t)lr) << 4));
            #pragma unroll
            for (int n2 = 0; n2 < 4; n2++) {
                const int n2p = whalf*4 + n2;
                uint32_t bfr[4];
                uint32_t ad = kRowB + (uint32_t)n2p*4096
                            + (((uint32_t)((ks << 1) | lb8) ^ (uint32_t)lr) << 4);
                LDSM4(bfr, ad);
                MMA16816(sacc[2*n2],     aq, bfr[0], bfr[1]);
                MMA16816(sacc[2*n2 + 1], aq, bfr[2], bfr[3]);
            }
        }
        __syncthreads();   // skvs complete before exp reads

        // ---- fused pv: pva += w[t] * V[t][d4..d4+3] (8 t per thread) ----
        {
            const char* vbuf = smc + ((c & 1) ? SV1 : SV0);
            const float* wrow = pwAll + c*128 + tg*8;
            #pragma unroll
            for (int j = 0; j < 8; j++) {
                int t = tg*8 + j;
                float wv = wrow[j];
                uint2 raw = *(const uint2*)(vbuf + t*256
                              + ((((uint32_t)(d4 >> 3)) ^ (uint32_t)(t & 7)) << 4)
                              + (d4 & 7)*2);
                float2 f0 = __bfloat1622float2(*reinterpret_cast<__nv_bfloat162*>(&raw.x));
                float2 f1 = __bfloat1622float2(*reinterpret_cast<__nv_bfloat162*>(&raw.y));
                pva.x += wv*f0.x; pva.y += wv*f0.y; pva.z += wv*f1.x; pva.w += wv*f1.y;
            }
        }

        // ---- exp2 with rank-1 s·K correction (base-2 logits throughout) ----
        uint32_t pf[4][4];
        #pragma unroll
        for (int nt = 0; nt < 8; nt++) {
            const int kcol = whalf*64 + (nt >> 1)*16 + ((nt & 1) << 3) + 2*(l & 3);
            float2 sk = *(const float2*)&skvs[kcol];
            float e0 = ex2f(sacc[nt][0] + sk.x);
            float e1 = ex2f(sacc[nt][1] + sk.y);
            float e2 = ex2f(sacc[nt][2] + sk.x);
            float e3 = ex2f(sacc[nt][3] + sk.y);
            lsum0 += e0 + e1;
            lsum1 += e2 + e3;
            pf[nt >> 1][(nt & 1)*2]     = bf2pack(e0, e1);
            pf[nt >> 1][(nt & 1)*2 + 1] = bf2pack(e2, e3);
        }

        // ---- O += P @ V (my key half, full d=128) ----
        #pragma unroll
        for (int np = 0; np < 8; np++) {
            #pragma unroll
            for (int ks = 0; ks < 4; ks++) {
                const int ksp = whalf*4 + ks;
                uint32_t bfr[4];
                uint32_t ad = vRowB + (uint32_t)ksp*4096
                            + (((uint32_t)((np << 1) | lb16) ^ (uint32_t)lr) << 4);
                LDSM4T(bfr, ad);
                MMA16816(oacc[2*np],     pf[ks], bfr[0], bfr[1]);
                MMA16816(oacc[2*np + 1], pf[ks], bfr[2], bfr[3]);
            }
        }
        __syncthreads();
    }

    // ---- row sums over my key half (quad reduce) ----
    lsum0 += __shfl_xor_sync(0xffffffffu, lsum0, 1);
    lsum0 += __shfl_xor_sync(0xffffffffu, lsum0, 2);
    lsum1 += __shfl_xor_sync(0xffffffffu, lsum1, 1);
    lsum1 += __shfl_xor_sync(0xffffffffu, lsum1, 2);

    const int r0r = mb + (l >> 2), r1r = r0r + 8;
    float* Opart = smf;            // [128 r][132], overwrites Q smem

    *(float4*)&pvacc[tg*128 + d4] = pva;

    if (whalf) {
        if ((l & 3) == 0) { lpart[r0r] = lsum0; lpart[r1r] = lsum1; }
        #pragma unroll
        for (int nt = 0; nt < 16; nt++) {
            int d0 = 8*nt + 2*(l & 3);
            Opart[r0r*132 + d0]     = oacc[nt][0];
            Opart[r0r*132 + d0 + 1] = oacc[nt][1];
            Opart[r1r*132 + d0]     = oacc[nt][2];
            Opart[r1r*132 + d0 + 1] = oacc[nt][3];
        }
    }
    __syncthreads();

    if (tid < 128) {
        float pvs = 0.f;
        #pragma unroll
        for (int g2 = 0; g2 < 16; g2++) pvs += pvacc[g2*128 + tid];
        sAdd[tid] = g_svec[tid & 63] + gv * pvs;   // = omg*s + gv*(pv_y + s)
    }
    __syncthreads();

    float* oT  = smf + OT_F;       // [128 d][PIT r], col = r ^ (((d>>3)&15)<<2)
    float* owT = smf + OWT/4;      // [64 cp][68 c]
    if (!whalf) {
        const float L0 = lsum0 + lpart[r0r];
        const float L1 = lsum1 + lpart[r1r];
        const float inv0 = omg / L0, inv1 = omg / L1;
        #pragma unroll
        for (int nt = 0; nt < 16; nt++) {
            int d0 = 8*nt + 2*(l & 3);
            int sw = nt << 2;
            oT[d0*PIT     + (r0r ^ sw)] = (oacc[nt][0] + Opart[r0r*132 + d0    ])*inv0 + sAdd[d0];
            oT[(d0+1)*PIT + (r0r ^ sw)] = (oacc[nt][1] + Opart[r0r*132 + d0 + 1])*inv0 + sAdd[d0+1];
            oT[d0*PIT     + (r1r ^ sw)] = (oacc[nt][2] + Opart[r1r*132 + d0    ])*inv1 + sAdd[d0];
            oT[(d0+1)*PIT + (r1r ^ sw)] = (oacc[nt][3] + Opart[r1r*132 + d0 + 1])*inv1 + sAdd[d0+1];
        }
    }
    for (int i = tid; i < 4096; i += 512) {
        int cp = i & 63, cc = i >> 6;
        owT[cp*68 + cc] = out_w[cc*64 + cp];
    }
    __syncthreads();

    // ---- GEMM2: out = oT @ out_w^T + out_b (512 threads, 4 rows each) ----
    const int tx = tid & 15, ty = tid >> 4;   // ty 0..31
    ULL facp[2][2][4];
    #pragma unroll
    for (int ws = 0; ws < 2; ws++)
        #pragma unroll
        for (int rp = 0; rp < 2; rp++)
            #pragma unroll
            for (int j = 0; j < 4; j++) facp[ws][rp][j] = 0ULL;

    #pragma unroll 2
    for (int cp = 0; cp < 64; cp++) {
        int swz0 = ((cp >> 3) & 15) << 2;
        int swz1 = (((cp + 64) >> 3) & 15) << 2;
        const float* r0 = oT + cp*PIT;
        const float* r1 = oT + (cp + 64)*PIT;
        ULL oa0 = *(const ULL*)(r0 + ((ty*4)     ^ swz0));
        ULL oa1 = *(const ULL*)(r0 + ((ty*4 + 2) ^ swz0));
        ULL oc0 = *(const ULL*)(r1 + ((ty*4)     ^ swz1));
        ULL oc1 = *(const ULL*)(r1 + ((ty*4 + 2) ^ swz1));
        float4 wf = *(const float4*)&owT[cp*68 + tx*4];
        ULL wd[4] = {dup2(wf.x), dup2(wf.y), dup2(wf.z), dup2(wf.w)};
        #pragma unroll
        for (int j = 0; j < 4; j++) {
            fma2(facp[0][0][j], oa0, wd[j]);
            fma2(facp[0][1][j], oa1, wd[j]);
            fma2(facp[1][0][j], oc0, wd[j]);
            fma2(facp[1][1][j], oc1, wd[j]);
        }
    }

    float ob4[4];
    #pragma unroll
    for (int j = 0; j < 4; j++) ob4[j] = out_b[tx*4 + j];

    #pragma unroll
    for (int ws = 0; ws < 2; ws++) {
        int w = h*2 + ws;
        #pragma unroll
        for (int rp = 0; rp < 2; rp++) {
            float2 f0 = unpk(facp[ws][rp][0]);
            float2 f1 = unpk(facp[ws][rp][1]);
            float2 f2 = unpk(facp[ws][rp][2]);
            float2 f3 = unpk(facp[ws][rp][3]);
            int sA = s0 + ty*4 + 2*rp;
            float4 lo = {f0.x+ob4[0], f1.x+ob4[1], f2.x+ob4[2], f3.x+ob4[3]};
            float4 hi = {f0.y+ob4[0], f1.y+ob4[1], f2.y+ob4[2], f3.y+ob4[3]};
            *(float4*)&out[(((size_t)b*1024 + sA    )*8 + w)*64 + tx*4] = lo;
            *(float4*)&out[(((size_t)b*1024 + sA + 1)*8 + w)*64 + tx*4] = hi;
        }
    }
}

// ---------------- launch ----------------
extern "C" void kernel_launch(void* const* d_in, const int* in_sizes, int n_in,
                              void* d_out, int out_size) {
    const float* x        = (const float*)d_in[0];
    const float* pos      = (const float*)d_in[1];
    const float* strength = (const float*)d_in[2];
    const int*   embid    = (const int*)  d_in[3];
    const float* qw       = (const float*)d_in[4];
    const float* kw       = (const float*)d_in[5];
    const float* vw       = (const float*)d_in[6];
    const float* pw1      = (const float*)d_in[7];
    const float* pb1      = (const float*)d_in[8];
    const float* pw2      = (const float*)d_in[9];
    const float* pb2      = (const float*)d_in[10];
    const float* hw       = (const float*)d_in[11];
    // d_in[12] = head_b (cancels in softmax)
    const float* gate     = (const float*)d_in[13];
    const float* ow       = (const float*)d_in[14];
    const float* ob       = (const float*)d_in[15];
    const float* sw       = (const float*)d_in[16];
    const float* sb       = (const float*)d_in[17];
    float* out = (float*)d_out;

    cudaFuncSetAttribute(k_attn, cudaFuncAttributeMaxDynamicSharedMemorySize, ATTN_SMEM);

    k_projposb<<<dim3(64, 6), 256>>>(x, qw, kw, vw, embid,
                                     pos, pw1, pb1, pw2, pb2, hw,
                                     strength, sw, sb);
    k_attn<<<dim3(8, 16), 512, ATTN_SMEM>>>(gate, ow, ob, out);
}

// round 17
// speedup vs baseline: 1.1809x; 1.1809x over previous
#include <cuda_runtime.h>
#include <cuda_bf16.h>
#include <cstdint>

typedef unsigned long long ULL;

// ---------------- helpers ----------------
__device__ __forceinline__ uint32_t smem_u32(const void* p) {
    uint32_t a;
    asm("{ .reg .u64 t; cvta.to.shared.u64 t, %1; cvt.u32.u64 %0, t; }" : "=r"(a) : "l"(p));
    return a;
}
__device__ __forceinline__ void fma2(ULL &d, ULL a, ULL b) {
    asm("fma.rn.f32x2 %0, %1, %2, %0;" : "+l"(d) : "l"(a), "l"(b));
}
__device__ __forceinline__ ULL dup2(float f) {
    ULL r; asm("mov.b64 %0, {%1, %1};" : "=l"(r) : "f"(f)); return r;
}
__device__ __forceinline__ float2 unpk(ULL v) {
    float2 r; asm("mov.b64 {%0, %1}, %2;" : "=f"(r.x), "=f"(r.y) : "l"(v)); return r;
}
__device__ __forceinline__ uint32_t bf2pack(float a, float b) {
    __nv_bfloat162 t = __floats2bfloat162_rn(a, b);
    return *reinterpret_cast<uint32_t*>(&t);
}
__device__ __forceinline__ float ex2f(float x) {
    float r; asm("ex2.approx.ftz.f32 %0, %1;" : "=f"(r) : "f"(x)); return r;
}

#define LDSM4(r, addr) \
    asm volatile("ldmatrix.sync.aligned.m8n8.x4.shared.b16 {%0,%1,%2,%3}, [%4];" \
        : "=r"((r)[0]), "=r"((r)[1]), "=r"((r)[2]), "=r"((r)[3]) : "r"(addr))
#define LDSM4T(r, addr) \
    asm volatile("ldmatrix.sync.aligned.m8n8.x4.trans.shared.b16 {%0,%1,%2,%3}, [%4];" \
        : "=r"((r)[0]), "=r"((r)[1]), "=r"((r)[2]), "=r"((r)[3]) : "r"(addr))
#define MMA16816(c, a, b0, b1) \
    asm volatile("mma.sync.aligned.m16n8k16.row.col.f32.bf16.bf16.f32 " \
        "{%0,%1,%2,%3}, {%4,%5,%6,%7}, {%8,%9}, {%0,%1,%2,%3};" \
        : "+f"((c)[0]), "+f"((c)[1]), "+f"((c)[2]), "+f"((c)[3]) \
        : "r"((a)[0]), "r"((a)[1]), "r"((a)[2]), "r"((a)[3]), "r"(b0), "r"(b1))

#define CP_ASYNC16(dst, src) \
    asm volatile("cp.async.cg.shared.global [%0], [%1], 16;" :: "r"(dst), "l"(src) : "memory")
#define CP_COMMIT() asm volatile("cp.async.commit_group;" ::: "memory")
#define CP_WAIT1()  asm volatile("cp.async.wait_group 1;" ::: "memory")
#define CP_WAIT0()  asm volatile("cp.async.wait_group 0;" ::: "memory")

// ---------------- problem constants ----------------
#define BB 4
#define SS 1024
#define HH 4
#define HD 128
#define PIT 132

// ---------------- device scratch ----------------
__device__ float g_svec[64];
__device__ __nv_bfloat16 g_qb[BB*HH*SS*HD];   // full q (y+s), scaled by log2e/sqrt(hd)
__device__ __nv_bfloat16 g_kb[BB*HH*SS*HD];   // y_k only (s cancels in softmax)
__device__ __nv_bfloat16 g_vb[BB*HH*SS*HD];   // y_v only (s re-added via sum(w)=1)
__device__ float g_pw[BB*HH*SS];              // normalized pos softmax weights

// ---------------- K0: strength projection (64 blocks, 1 channel each) ----------------
__global__ __launch_bounds__(128) void k_svec(
    const float* __restrict__ strength,
    const float* __restrict__ str_w, const float* __restrict__ str_b)
{
    __shared__ float red[4];
    const int d = blockIdx.x, tid = threadIdx.x;
    const int l = tid & 31, w = tid >> 5;
    float4 a = *(const float4*)(str_w + d*512 + tid*4);
    float4 s4 = *(const float4*)(strength + tid*4);
    float s = a.x*s4.x + a.y*s4.y + a.z*s4.z + a.w*s4.w;
    #pragma unroll
    for (int ofs = 1; ofs < 32; ofs <<= 1)
        s += __shfl_xor_sync(0xffffffffu, s, ofs);
    if (l == 0) red[w] = s;
    __syncthreads();
    if (tid == 0) g_svec[d] = red[0] + red[1] + red[2] + red[3] + str_b[d];
}

// ---------------- K1: q/k/v projections (bf16 MMA) + pos branch (by==4) ----------------
__global__ __launch_bounds__(256) void k_projposb(
    const float* __restrict__ x,
    const float* __restrict__ qw, const float* __restrict__ kw,
    const float* __restrict__ vw, const int* __restrict__ embid,
    const float* __restrict__ pos,
    const float* __restrict__ w1, const float* __restrict__ b1,
    const float* __restrict__ w2, const float* __restrict__ b2,
    const float* __restrict__ hw)
{
    __shared__ __align__(16) char psm[16384 + 3*8192 + 256];
    const int tid = threadIdx.x;

    if (blockIdx.y == 4) {        // ---- positional softmax weights ----
        if (blockIdx.x >= 16) return;
        float* sn  = (float*)psm;        // 1024
        float* red = sn + 1024;          // 256
        const int bh = blockIdx.x, bp = bh >> 2, hp = bh & 3;

        float hwv[8];
        #pragma unroll
        for (int d = 0; d < 8; d++) hwv[d] = hw[hp*8 + d];

        for (int s = tid; s < 1024; s += 256) {
            int idx = bp*1024 + s;
            float p0 = pos[idx*3+0], p1 = pos[idx*3+1], p2 = pos[idx*3+2];
            float h1[3];
            #pragma unroll
            for (int j = 0; j < 3; j++)
                h1[j] = fmaxf(0.f, w1[j*3+0]*p0 + w1[j*3+1]*p1 + w1[j*3+2]*p2 + b1[j]);
            float a = 0.f;
            #pragma unroll
            for (int d = 0; d < 8; d++) {
                float ph = w2[d*3+0]*h1[0] + w2[d*3+1]*h1[1] + w2[d*3+2]*h1[2] + b2[d];
                a += ph * hwv[d];
            }
            sn[s] = -a;     // head_b cancels in softmax
        }
        __syncthreads();

        float mx = fmaxf(fmaxf(sn[tid], sn[tid+256]), fmaxf(sn[tid+512], sn[tid+768]));
        red[tid] = mx; __syncthreads();
        for (int st = 128; st > 0; st >>= 1) { if (tid < st) red[tid] = fmaxf(red[tid], red[tid+st]); __syncthreads(); }
        mx = red[0]; __syncthreads();

        float e0 = __expf(sn[tid      ] - mx), e1 = __expf(sn[tid + 256] - mx);
        float e2 = __expf(sn[tid + 512] - mx), e3 = __expf(sn[tid + 768] - mx);
        red[tid] = e0 + e1 + e2 + e3; __syncthreads();
        for (int st = 128; st > 0; st >>= 1) { if (tid < st) red[tid] += red[tid+st]; __syncthreads(); }
        float inv = 1.f / red[0];

        size_t base = (size_t)bh*1024;
        g_pw[base + tid      ] = e0 * inv;
        g_pw[base + tid + 256] = e1 * inv;
        g_pw[base + tid + 512] = e2 * inv;
        g_pw[base + tid + 768] = e3 * inv;
        return;
    }

    // ---- projections: 128 m-rows (16 s x 8 w) at s0 = bx*16 ----
    float* sAdd = (float*)(psm + 16384 + 24576);
    const uint32_t sbp = smem_u32(psm);
    const int bx = blockIdx.x, b = blockIdx.y;
    const int s0 = bx * 16;
    const int wid = tid >> 5, l = tid & 31;
    const int id = embid[0];

    if (tid < 64) sAdd[tid] = g_svec[tid];

    {
        const float* xb = x + (size_t)(b*64)*8192 + (size_t)s0*8;
        for (int i = tid; i < 2048; i += 256) {
            int c = i >> 5, mf = (i & 31) << 2;
            float4 v = *(const float4*)(xb + (size_t)c*8192 + mf);
            uint2 u = { bf2pack(v.x, v.y), bf2pack(v.z, v.w) };
            *(uint2*)(psm + c*256 + ((((mf>>3)) ^ (c & 7)) << 4) + (mf & 7)*2) = u;
        }
    }
    {
        const float* es[3] = { qw + (size_t)id*4096, kw + (size_t)id*4096, vw + (size_t)id*4096 };
        #pragma unroll
        for (int e = 0; e < 3; e++) {
            char* eb = psm + 16384 + e*8192;
            for (int i = tid; i < 1024; i += 256) {
                int d = i >> 4, cf = (i & 15) << 2;
                float4 v = *(const float4*)(es[e] + d*64 + cf);
                uint2 u = { bf2pack(v.x, v.y), bf2pack(v.z, v.w) };
                *(uint2*)(eb + d*128 + (((cf>>3) ^ (d & 7)) << 4) + (cf & 7)*2) = u;
            }
        }
    }
    __syncthreads();

    const int lr = l & 7, lb8 = (l >> 3) & 1, lb16 = l >> 4;
    const int mb = wid * 16;

    uint32_t af[4][4];
    #pragma unroll
    for (int ks = 0; ks < 4; ks++) {
        uint32_t ad = sbp + (uint32_t)(ks*16 + lr + (lb16 << 3))*256
                    + ((((uint32_t)(mb >> 3) + (uint32_t)lb8) ^ (uint32_t)lr) << 4);
        LDSM4T(af[ks], ad);
    }

    float cc[3][8][4];
    #pragma unroll
    for (int e = 0; e < 3; e++)
        #pragma unroll
        for (int nt = 0; nt < 8; nt++)
            #pragma unroll
            for (int j = 0; j < 4; j++) cc[e][nt][j] = 0.f;

    #pragma unroll
    for (int ks = 0; ks < 4; ks++) {
        #pragma unroll
        for (int e = 0; e < 3; e++) {
            const uint32_t ebB = sbp + 16384 + (uint32_t)e*8192
                               + (uint32_t)(lr + (lb16 << 3))*128;
            #pragma unroll
            for (int n4 = 0; n4 < 4; n4++) {
                uint32_t bfr[4];
                uint32_t ad = ebB + (uint32_t)n4*2048
                            + ((((uint32_t)(ks << 1) | (uint32_t)lb8) ^ (uint32_t)lr) << 4);
                LDSM4(bfr, ad);
                MMA16816(cc[e][n4*2],     af[ks], bfr[0], bfr[1]);
                MMA16816(cc[e][n4*2 + 1], af[ks], bfr[2], bfr[3]);
            }
        }
    }

    const float SC = 0.12751744817759326f;   // log2(e)/sqrt(128)
    const int q0 = l & 3, lr2 = l >> 2;
    #pragma unroll
    for (int rr = 0; rr < 2; rr++) {
        int m = mb + lr2 + rr*8;
        int sl = m >> 3, w = m & 7;
        int h = w >> 1;
        int bh = b*4 + h;
        int jb = (w & 1) << 6;
        size_t base = ((size_t)bh*1024 + (s0 + sl))*128 + jb;
        #pragma unroll
        for (int nt = 0; nt < 8; nt++) {
            int d = nt*8 + q0*2;
            float v0 = cc[0][nt][rr*2], v1 = cc[0][nt][rr*2 + 1];
            *(uint32_t*)&g_qb[base + d] = bf2pack((v0 + sAdd[d])*SC, (v1 + sAdd[d+1])*SC);
            *(uint32_t*)&g_kb[base + d] = bf2pack(cc[1][nt][rr*2], cc[1][nt][rr*2 + 1]);
            *(uint32_t*)&g_vb[base + d] = bf2pack(cc[2][nt][rr*2], cc[2][nt][rr*2 + 1]);
        }
    }
}

// ---------------- K2: bf16 mma.sync flash attention + fused pv ----------------
#define SQO 0
#define SK0 32768
#define SK1 65536
#define SV0 98304
#define SV1 131072
#define SADD 165888
#define LPART 166400
#define OWT 166912
#define PVACC 184832
#define PWALL 193024
#define OT_F 24576          // float index of byte 98304
#define ATTN_SMEM 197120

__global__ __launch_bounds__(512) void k_attn(
    const float* __restrict__ gate, const float* __restrict__ out_w,
    const float* __restrict__ out_b, float* __restrict__ out)
{
    extern __shared__ char smc[];
    float* smf = (float*)smc;
    const uint32_t sb = smem_u32(smc);
    const int stile = blockIdx.x, bh = blockIdx.y;
    const int b = bh >> 2, h = bh & 3;
    const int s0 = stile * 128;
    const int tid = threadIdx.x, wid = tid >> 5, l = tid & 31;
    const int lr = l & 7, lb8 = (l >> 3) & 1, lb16 = l >> 4;
    const int wm = wid & 7, whalf = wid >> 3;   // key-half split

    const float gv  = 1.f / (1.f + __expf(-gate[h]));
    const float omg = 1.f - gv;
    float* sAdd  = (float*)(smc + SADD);
    float* lpart = (float*)(smc + LPART);
    float* pvacc = (float*)(smc + PVACC);
    float* pwAll = (float*)(smc + PWALL);   // all 1024 pos weights for this bh

    const int tg = tid >> 5;
    const int d4 = l << 2;
    float4 pva = {0.f, 0.f, 0.f, 0.f};

    // ---- preload pos weights (once) ----
    for (int i = tid; i < 1024; i += 512) pwAll[i] = g_pw[(size_t)bh*1024 + i];

    // ---- stage Q (once) ----
    const __nv_bfloat16* Qb = g_qb + (size_t)bh*131072 + (size_t)s0*128;
    for (int i = tid; i < 2048; i += 512) {
        int r = i >> 4, cc = i & 15;
        *(uint4*)(smc + SQO + r*256 + ((cc ^ (r & 7)) << 4)) =
            *(const uint4*)(Qb + (size_t)r*128 + cc*8);
    }

    const __nv_bfloat16* Kb = g_kb + (size_t)bh*131072;
    const __nv_bfloat16* Vb = g_vb + (size_t)bh*131072;

    // prefetch chunk 0
    {
        const uint32_t kB = sb + SK0, vB = sb + SV0;
        for (int i = tid; i < 2048; i += 512) {
            int r = i >> 4, cc = i & 15;
            uint32_t sw = (uint32_t)(r*256 + ((cc ^ (r & 7)) << 4));
            CP_ASYNC16(kB + sw, Kb + (size_t)r*128 + cc*8);
            CP_ASYNC16(vB + sw, Vb + (size_t)r*128 + cc*8);
        }
        CP_COMMIT();
    }
    __syncthreads();   // Q + pwAll visible

    const int mb = wm * 16;
    const int arow = mb + lr + (lb8 << 3);
    const uint32_t aBase = sb + SQO + arow*256;

    float oacc[16][4];
    #pragma unroll
    for (int i = 0; i < 16; i++)
        #pragma unroll
        for (int j = 0; j < 4; j++) oacc[i][j] = 0.f;
    float lsum0 = 0.f, lsum1 = 0.f;

    for (int c = 0; c < 8; c++) {
        if (c < 7) {
            const int t0n = (c + 1) * 128;
            const uint32_t kB = sb + (((c + 1) & 1) ? SK1 : SK0);
            const uint32_t vB = sb + (((c + 1) & 1) ? SV1 : SV0);
            for (int i = tid; i < 2048; i += 512) {
                int r = i >> 4, cc = i & 15;
                uint32_t sw = (uint32_t)(r*256 + ((cc ^ (r & 7)) << 4));
                CP_ASYNC16(kB + sw, Kb + (size_t)(t0n + r)*128 + cc*8);
                CP_ASYNC16(vB + sw, Vb + (size_t)(t0n + r)*128 + cc*8);
            }
            CP_COMMIT();
            CP_WAIT1();
        } else {
            CP_WAIT0();
        }
        __syncthreads();

        const uint32_t kRowB = sb + ((c & 1) ? SK1 : SK0) + (uint32_t)(lr + (lb16 << 3))*256;
        const uint32_t vRowB = sb + ((c & 1) ? SV1 : SV0) + (uint32_t)(lr + (lb8  << 3))*256;

        // ---- S = Q @ K^T (m16 x my 64-key half) ----
        float sacc[8][4];
        #pragma unroll
        for (int i = 0; i < 8; i++)
            #pragma unroll
            for (int j = 0; j < 4; j++) sacc[i][j] = 0.f;

        #pragma unroll
        for (int ks = 0; ks < 8; ks++) {
            uint32_t aq[4];
            LDSM4(aq, aBase + (((uint32_t)((ks << 1) | lb16) ^ (uint32_t)lr) << 4));
            #pragma unroll
            for (int n2 = 0; n2 < 4; n2++) {
                const int n2p = whalf*4 + n2;
                uint32_t bfr[4];
                uint32_t ad = kRowB + (uint32_t)n2p*4096
                            + (((uint32_t)((ks << 1) | lb8) ^ (uint32_t)lr) << 4);
                LDSM4(bfr, ad);
                MMA16816(sacc[2*n2],     aq, bfr[0], bfr[1]);
                MMA16816(sacc[2*n2 + 1], aq, bfr[2], bfr[3]);
            }
        }

        // ---- fused pv: pva += w[t] * V[t][d4..d4+3] (8 t per thread) ----
        {
            const char* vbuf = smc + ((c & 1) ? SV1 : SV0);
            const float* wrow = pwAll + c*128 + tg*8;
            #pragma unroll
            for (int j = 0; j < 8; j++) {
                int t = tg*8 + j;
                float wv = wrow[j];
                uint2 raw = *(const uint2*)(vbuf + t*256
                              + ((((uint32_t)(d4 >> 3)) ^ (uint32_t)(t & 7)) << 4)
                              + (d4 & 7)*2);
                float2 f0 = __bfloat1622float2(*reinterpret_cast<__nv_bfloat162*>(&raw.x));
                float2 f1 = __bfloat1622float2(*reinterpret_cast<__nv_bfloat162*>(&raw.y));
                pva.x += wv*f0.x; pva.y += wv*f0.y; pva.z += wv*f1.x; pva.w += wv*f1.y;
            }
        }

        // ---- exp2 (q pre-scaled by log2e; C=0 — row-const q·s cancelled) ----
        uint32_t pf[4][4];
        #pragma unroll
        for (int nt = 0; nt < 8; nt++) {
            float e0 = ex2f(sacc[nt][0]);
            float e1 = ex2f(sacc[nt][1]);
            float e2 = ex2f(sacc[nt][2]);
            float e3 = ex2f(sacc[nt][3]);
            lsum0 += e0 + e1;
            lsum1 += e2 + e3;
            pf[nt >> 1][(nt & 1)*2]     = bf2pack(e0, e1);
            pf[nt >> 1][(nt & 1)*2 + 1] = bf2pack(e2, e3);
        }

        // ---- O += P @ V (my key half, full d=128) ----
        #pragma unroll
        for (int np = 0; np < 8; np++) {
            #pragma unroll
            for (int ks = 0; ks < 4; ks++) {
                const int ksp = whalf*4 + ks;
                uint32_t bfr[4];
                uint32_t ad = vRowB + (uint32_t)ksp*4096
                            + (((uint32_t)((np << 1) | lb16) ^ (uint32_t)lr) << 4);
                LDSM4T(bfr, ad);
                MMA16816(oacc[2*np],     pf[ks], bfr[0], bfr[1]);
                MMA16816(oacc[2*np + 1], pf[ks], bfr[2], bfr[3]);
            }
        }
        __syncthreads();
    }

    // ---- row sums over my key half (quad reduce) ----
    lsum0 += __shfl_xor_sync(0xffffffffu, lsum0, 1);
    lsum0 += __shfl_xor_sync(0xffffffffu, lsum0, 2);
    lsum1 += __shfl_xor_sync(0xffffffffu, lsum1, 1);
    lsum1 += __shfl_xor_sync(0xffffffffu, lsum1, 2);

    const int r0r = mb + (l >> 2), r1r = r0r + 8;
    float* Opart = smf;            // [128 r][132], overwrites Q smem

    *(float4*)&pvacc[tg*128 + d4] = pva;

    if (whalf) {
        if ((l & 3) == 0) { lpart[r0r] = lsum0; lpart[r1r] = lsum1; }
        #pragma unroll
        for (int nt = 0; nt < 16; nt++) {
            int d0 = 8*nt + 2*(l & 3);
            Opart[r0r*132 + d0]     = oacc[nt][0];
            Opart[r0r*132 + d0 + 1] = oacc[nt][1];
            Opart[r1r*132 + d0]     = oacc[nt][2];
            Opart[r1r*132 + d0 + 1] = oacc[nt][3];
        }
    }
    __syncthreads();

    if (tid < 128) {
        float pvs = 0.f;
        #pragma unroll
        for (int g2 = 0; g2 < 16; g2++) pvs += pvacc[g2*128 + tid];
        sAdd[tid] = g_svec[tid & 63] + gv * pvs;   // = omg*s + gv*(pv_y + s)
    }
    __syncthreads();

    float* oT  = smf + OT_F;       // [128 d][PIT r], col = r ^ (((d>>3)&15)<<2)
    float* owT = smf + OWT/4;      // [64 cp][68 c]
    if (!whalf) {
        const float L0 = lsum0 + lpart[r0r];
        const float L1 = lsum1 + lpart[r1r];
        const float inv0 = omg / L0, inv1 = omg / L1;
        #pragma unroll
        for (int nt = 0; nt < 16; nt++) {
            int d0 = 8*nt + 2*(l & 3);
            int sw = nt << 2;
            oT[d0*PIT     + (r0r ^ sw)] = (oacc[nt][0] + Opart[r0r*132 + d0    ])*inv0 + sAdd[d0];
            oT[(d0+1)*PIT + (r0r ^ sw)] = (oacc[nt][1] + Opart[r0r*132 + d0 + 1])*inv0 + sAdd[d0+1];
            oT[d0*PIT     + (r1r ^ sw)] = (oacc[nt][2] + Opart[r1r*132 + d0    ])*inv1 + sAdd[d0];
            oT[(d0+1)*PIT + (r1r ^ sw)] = (oacc[nt][3] + Opart[r1r*132 + d0 + 1])*inv1 + sAdd[d0+1];
        }
    }
    for (int i = tid; i < 4096; i += 512) {
        int cp = i & 63, cc = i >> 6;
        owT[cp*68 + cc] = out_w[cc*64 + cp];
    }
    __syncthreads();

    // ---- GEMM2: out = oT @ out_w^T + out_b (512 threads, 4 rows each) ----
    const int tx = tid & 15, ty = tid >> 4;   // ty 0..31
    ULL facp[2][2][4];
    #pragma unroll
    for (int ws = 0; ws < 2; ws++)
        #pragma unroll
        for (int rp = 0; rp < 2; rp++)
            #pragma unroll
            for (int j = 0; j < 4; j++) facp[ws][rp][j] = 0ULL;

    #pragma unroll 2
    for (int cp = 0; cp < 64; cp++) {
        int swz0 = ((cp >> 3) & 15) << 2;
        int swz1 = (((cp + 64) >> 3) & 15) << 2;
        const float* r0 = oT + cp*PIT;
        const float* r1 = oT + (cp + 64)*PIT;
        ULL oa0 = *(const ULL*)(r0 + ((ty*4)     ^ swz0));
        ULL oa1 = *(const ULL*)(r0 + ((ty*4 + 2) ^ swz0));
        ULL oc0 = *(const ULL*)(r1 + ((ty*4)     ^ swz1));
        ULL oc1 = *(const ULL*)(r1 + ((ty*4 + 2) ^ swz1));
        float4 wf = *(const float4*)&owT[cp*68 + tx*4];
        ULL wd[4] = {dup2(wf.x), dup2(wf.y), dup2(wf.z), dup2(wf.w)};
        #pragma unroll
        for (int j = 0; j < 4; j++) {
            fma2(facp[0][0][j], oa0, wd[j]);
            fma2(facp[0][1][j], oa1, wd[j]);
            fma2(facp[1][0][j], oc0, wd[j]);
            fma2(facp[1][1][j], oc1, wd[j]);
        }
    }

    float ob4[4];
    #pragma unroll
    for (int j = 0; j < 4; j++) ob4[j] = out_b[tx*4 + j];

    #pragma unroll
    for (int ws = 0; ws < 2; ws++) {
        int w = h*2 + ws;
        #pragma unroll
        for (int rp = 0; rp < 2; rp++) {
            float2 f0 = unpk(facp[ws][rp][0]);
            float2 f1 = unpk(facp[ws][rp][1]);
            float2 f2 = unpk(facp[ws][rp][2]);
            float2 f3 = unpk(facp[ws][rp][3]);
            int sA = s0 + ty*4 + 2*rp;
            float4 lo = {f0.x+ob4[0], f1.x+ob4[1], f2.x+ob4[2], f3.x+ob4[3]};
            float4 hi = {f0.y+ob4[0], f1.y+ob4[1], f2.y+ob4[2], f3.y+ob4[3]};
            *(float4*)&out[(((size_t)b*1024 + sA    )*8 + w)*64 + tx*4] = lo;
            *(float4*)&out[(((size_t)b*1024 + sA + 1)*8 + w)*64 + tx*4] = hi;
        }
    }
}

// ---------------- launch ----------------
extern "C" void kernel_launch(void* const* d_in, const int* in_sizes, int n_in,
                              void* d_out, int out_size) {
    const float* x        = (const float*)d_in[0];
    const float* pos      = (const float*)d_in[1];
    const float* strength = (const float*)d_in[2];
    const int*   embid    = (const int*)  d_in[3];
    const float* qw       = (const float*)d_in[4];
    const float* kw       = (const float*)d_in[5];
    const float* vw       = (const float*)d_in[6];
    const float* pw1      = (const float*)d_in[7];
    const float* pb1      = (const float*)d_in[8];
    const float* pw2      = (const float*)d_in[9];
    const float* pb2      = (const float*)d_in[10];
    const float* hw       = (const float*)d_in[11];
    // d_in[12] = head_b (cancels in softmax)
    const float* gate     = (const float*)d_in[13];
    const float* ow       = (const float*)d_in[14];
    const float* ob       = (const float*)d_in[15];
    const float* sw       = (const float*)d_in[16];
    const float* sb       = (const float*)d_in[17];
    float* out = (float*)d_out;

    cudaFuncSetAttribute(k_attn, cudaFuncAttributeMaxDynamicSharedMemorySize, ATTN_SMEM);

    k_svec<<<64, 128>>>(strength, sw, sb);
    k_projposb<<<dim3(64, 5), 256>>>(x, qw, kw, vw, embid,
                                     pos, pw1, pb1, pw2, pb2, hw);
    k_attn<<<dim3(8, 16), 512, ATTN_SMEM>>>(gate, ow, ob, out);
}